// round 11
// baseline (speedup 1.0000x reference)
#include <cuda_runtime.h>
#include <math.h>

// ---------------------------------------------------------------------------
// HSGNN forward, GB300.  Sparse-bitmask pipeline, 5 kernels.
// K1: flat word-per-thread adj scan (no smem, no barriers, 8-deep MLP).
// ---------------------------------------------------------------------------

#define NN 5000
#define WPR 157      // ceil(5000/32) words per bitmask row
#define WPRP 160     // padded words per row
#define WQ 40        // WPRP/4
#define DOUT 16
#define NCLS 100

__device__ unsigned g_bits[3][NN * WPRP];   // per-meta-path adjacency bitmasks
__device__ unsigned g_union[NN * WPRP];     // union pattern
__device__ int      g_deg[4 * NN];          // degrees: k=0,1,2, union
__device__ float    g_dinv[3][NN];          // D^{-1/2} per meta-path
__device__ float    g_dinvu[NN];            // D^{-1/2} for union pattern
__device__ float    g_XWs[3][NN * DOUT];    // dinv[k][i] * (features @ W_gnn[k])[i]
__device__ float    g_fs[NN * DOUT];        // dinvu[i] * f_meta[i]
__device__ float    g_atta[NN * 4];         // a[i,k] (padded stride 4)
__device__ float    g_attb[NN * 4];         // b[j,k]

// ---------------------------------------------------------------------------
// K1: one thread = one mask word (8 consecutive float4 of one adj row).
// Fully coalesced (warp = 4 KB contiguous), 8 loads in flight per thread,
// no smem, no syncthreads.  Also zeroes the degree counters.
// ---------------------------------------------------------------------------
__global__ void k_bits(const float4* __restrict__ adj4) {
    int x = blockIdx.x * 256 + threadIdx.x;
    if (x < 4 * NN) g_deg[x] = 0;
    if (x >= 3 * NN * WPRP) return;
    int w = x % WPRP;
    int r = x / WPRP;                          // r = k*NN + i
    unsigned word = 0;
    if (w < WPR) {
        const float4* rp = adj4 + (size_t)r * 1250 + w * 8;
        int lim = 1250 - w * 8;                // 8 except last word (2)
        #pragma unroll
        for (int q = 0; q < 8; q++) {
            if (q < lim) {
                float4 v = __ldcs(rp + q);
                unsigned nb = (v.x != 0.f ? 1u : 0u) | (v.y != 0.f ? 2u : 0u) |
                              (v.z != 0.f ? 4u : 0u) | (v.w != 0.f ? 8u : 0u);
                word |= nb << (q * 4);
            }
        }
    }
    ((unsigned*)g_bits)[x] = word;
}

// ---------------------------------------------------------------------------
// K2: union = OR of the 3 mask arrays (uint4, L2-hot) + degree REDGs.
// ---------------------------------------------------------------------------
__global__ void k_union() {
    int x = blockIdx.x * 256 + threadIdx.x;    // over NN*WQ = 200,000
    if (x >= NN * WQ) return;
    uint4 a = ((const uint4*)g_bits[0])[x];
    uint4 b = ((const uint4*)g_bits[1])[x];
    uint4 c = ((const uint4*)g_bits[2])[x];
    uint4 u = make_uint4(a.x | b.x | c.x, a.y | b.y | c.y,
                         a.z | b.z | c.z, a.w | b.w | c.w);
    ((uint4*)g_union)[x] = u;
    int i = x / WQ;
    int ca = __popc(a.x) + __popc(a.y) + __popc(a.z) + __popc(a.w);
    int cb = __popc(b.x) + __popc(b.y) + __popc(b.z) + __popc(b.w);
    int cc = __popc(c.x) + __popc(c.y) + __popc(c.z) + __popc(c.w);
    int cu = __popc(u.x) + __popc(u.y) + __popc(u.z) + __popc(u.w);
    if (ca) atomicAdd(&g_deg[i], ca);
    if (cb) atomicAdd(&g_deg[NN + i], cb);
    if (cc) atomicAdd(&g_deg[2 * NN + i], cc);
    if (cu) atomicAdd(&g_deg[3 * NN + i], cu);
}

// ---------------------------------------------------------------------------
// K3: XWs[k][i] = dinv[k][i] * (features[i] @ W_gnn[k]); also emits
// g_dinv / g_dinvu.  Register tile: 4 rows/thread share each W load.
// 192 threads = (rq:4) x (k:3) x (o:16); 16 rows/block.
// ---------------------------------------------------------------------------
__global__ void k_xw(const float* __restrict__ feat, const float* __restrict__ W) {
    __shared__ float sf[16 * 512];             // 32 KB
    int i0 = blockIdx.x * 16;
    for (int x = threadIdx.x; x < 16 * 128; x += 192) {
        int r = x >> 7, c = x & 127;
        int gi = i0 + r;
        float4 v = make_float4(0.f, 0.f, 0.f, 0.f);
        if (gi < NN) v = ((const float4*)feat)[(size_t)gi * 128 + c];
        ((float4*)sf)[x] = v;
    }
    __syncthreads();

    int t = threadIdx.x;
    int o = t & 15;
    int k = (t >> 4) % 3;
    int rq = t / 48;                           // 0..3
    const float* wp = W + k * (512 * 16) + o;
    const float* f0 = sf + (rq * 4 + 0) * 512;
    const float* f1 = f0 + 512;
    const float* f2 = f1 + 512;
    const float* f3 = f2 + 512;
    float a0 = 0.f, a1 = 0.f, a2 = 0.f, a3 = 0.f;
    #pragma unroll 4
    for (int d = 0; d < 512; d += 4) {
        float w0 = wp[(d + 0) * 16];
        float w1 = wp[(d + 1) * 16];
        float w2 = wp[(d + 2) * 16];
        float w3 = wp[(d + 3) * 16];
        float4 x0 = *(const float4*)(f0 + d);
        float4 x1 = *(const float4*)(f1 + d);
        float4 x2 = *(const float4*)(f2 + d);
        float4 x3 = *(const float4*)(f3 + d);
        a0 = fmaf(x0.x, w0, fmaf(x0.y, w1, fmaf(x0.z, w2, fmaf(x0.w, w3, a0))));
        a1 = fmaf(x1.x, w0, fmaf(x1.y, w1, fmaf(x1.z, w2, fmaf(x1.w, w3, a1))));
        a2 = fmaf(x2.x, w0, fmaf(x2.y, w1, fmaf(x2.z, w2, fmaf(x2.w, w3, a2))));
        a3 = fmaf(x3.x, w0, fmaf(x3.y, w1, fmaf(x3.z, w2, fmaf(x3.w, w3, a3))));
    }
    int gi = i0 + rq * 4;
    float acc[4] = {a0, a1, a2, a3};
    #pragma unroll
    for (int r = 0; r < 4; r++) {
        if (gi + r < NN) {
            float dv = rsqrtf((float)(g_deg[k * NN + gi + r] + 1));
            g_XWs[k][(gi + r) * DOUT + o] = acc[r] * dv;
            if (o == 0) g_dinv[k][gi + r] = dv;
        }
    }
    if (t < 16 && i0 + t < NN)
        g_dinvu[i0 + t] = rsqrtf((float)(g_deg[3 * NN + i0 + t] + 1));
}

// ---------------------------------------------------------------------------
// Deterministic nonzero-list build within an NT-thread group.
// ---------------------------------------------------------------------------
template <int NT>
__device__ __forceinline__ void build_list(const unsigned* __restrict__ src, int lt,
                                           unsigned* s_w, int* s_cntw, int* s_base,
                                           int* s_list, int* s_n) {
    for (int w = lt; w < WPRP; w += NT) {
        unsigned m = (w < WPR) ? src[w] : 0u;
        s_w[w] = m;
        s_cntw[w] = __popc(m);
    }
    __syncthreads();
    if (lt < 32) {
        int run = 0;
        #pragma unroll
        for (int g = 0; g < 5; g++) {
            int w = g * 32 + lt;
            int c = s_cntw[w];
            int x = c;
            #pragma unroll
            for (int off = 1; off < 32; off <<= 1) {
                int y = __shfl_up_sync(0xffffffffu, x, off);
                if (lt >= off) x += y;
            }
            s_base[w] = run + x - c;
            run += __shfl_sync(0xffffffffu, x, 31);
        }
        if (lt == 0) *s_n = run;
    }
    __syncthreads();
    for (int w = lt; w < WPR; w += NT) {
        unsigned m = s_w[w];
        int base = s_base[w];
        int jb = w * 32;
        while (m) {
            int b = __ffs(m) - 1; m &= m - 1;
            s_list[base++] = jb + b;
        }
    }
    __syncthreads();
}

// float4 gather-accumulate over list, SUBS parallel streams, 2-deep pipeline.
template <int SUBS>
__device__ __forceinline__ float4 gather4(const float4* __restrict__ X4,
                                          const int* __restrict__ list,
                                          int E, int sub, int d4) {
    float4 a0 = make_float4(0.f, 0.f, 0.f, 0.f);
    float4 a1 = make_float4(0.f, 0.f, 0.f, 0.f);
    int e = sub;
    for (; e + SUBS < E; e += 2 * SUBS) {
        int j0 = list[e], j1 = list[e + SUBS];
        float4 v0 = X4[j0 * 4 + d4];
        float4 v1 = X4[j1 * 4 + d4];
        a0.x += v0.x; a0.y += v0.y; a0.z += v0.z; a0.w += v0.w;
        a1.x += v1.x; a1.y += v1.y; a1.z += v1.z; a1.w += v1.w;
    }
    if (e < E) {
        float4 v = X4[list[e] * 4 + d4];
        a0.x += v.x; a0.y += v.y; a0.z += v.z; a0.w += v.w;
    }
    a0.x += a1.x; a0.y += a1.y; a0.z += a1.z; a0.w += a1.w;
    return a0;
}

// Reduce within warp (8 subs x float4) -> s_part[warp][16].
__device__ __forceinline__ void reduce4(float4 acc, int lane, int warp, int d4,
                                        float (*s_part)[16]) {
    #pragma unroll
    for (int off = 4; off < 32; off <<= 1) {
        acc.x += __shfl_xor_sync(0xffffffffu, acc.x, off);
        acc.y += __shfl_xor_sync(0xffffffffu, acc.y, off);
        acc.z += __shfl_xor_sync(0xffffffffu, acc.z, off);
        acc.w += __shfl_xor_sync(0xffffffffu, acc.w, off);
    }
    if (lane < 4) {
        s_part[warp][d4 * 4 + 0] = acc.x;
        s_part[warp][d4 * 4 + 1] = acc.y;
        s_part[warp][d4 * 4 + 2] = acc.z;
        s_part[warp][d4 * 4 + 3] = acc.w;
    }
}

// ---------------------------------------------------------------------------
// K4: 3 meta-path GCN convs (warpgroup per k) + max -> f_meta, scaled f_s,
// attention projections. Block per row, 384 threads.
// ---------------------------------------------------------------------------
__global__ void k_hatt(const float* __restrict__ bgnn, const float* __restrict__ attw,
                       float* __restrict__ fmeta) {
    int i = blockIdx.x;
    int t = threadIdx.x;
    int k = t >> 7;               // warpgroup = meta-path
    int lt = t & 127;
    int lane = lt & 31, warp = lt >> 5;
    int d4 = lt & 3, sub = lt >> 2;

    __shared__ unsigned s_w[3][WPRP];
    __shared__ int s_cntw[3][WPRP];
    __shared__ int s_base[3][WPRP];
    __shared__ int s_list[3][320];
    __shared__ int s_n[3];
    __shared__ float s_part[3][4][16];
    __shared__ float s_h[3][16];

    build_list<128>(&g_bits[k][i * WPRP], lt, s_w[k], s_cntw[k], s_base[k],
                    s_list[k], &s_n[k]);

    float4 acc = gather4<32>((const float4*)g_XWs[k], s_list[k], s_n[k], sub, d4);
    reduce4(acc, lane, warp, d4, s_part[k]);
    __syncthreads();

    if (lt < 16) {
        const float* Xs = g_XWs[k];
        float s = s_part[k][0][lt] + s_part[k][1][lt] +
                  s_part[k][2][lt] + s_part[k][3][lt];
        float di = g_dinv[k][i];
        s_h[k][lt] = fmaf(di, s + Xs[i * DOUT + lt], bgnn[k * 16 + lt]);
    }
    __syncthreads();

    if (t < 32) {
        float best = 0.f;
        if (t < 16) {
            best = fmaxf(s_h[0][t], fmaxf(s_h[1][t], s_h[2][t]));
            fmeta[i * DOUT + t] = best;
            g_fs[i * DOUT + t] = g_dinvu[i] * best;
        }
        #pragma unroll
        for (int kk = 0; kk < 3; kk++) {
            float va = (t < 16) ? best * attw[kk * 32 + t] : 0.f;
            float vb = (t < 16) ? best * attw[kk * 32 + 16 + t] : 0.f;
            #pragma unroll
            for (int off = 8; off >= 1; off >>= 1) {
                va += __shfl_xor_sync(0xffffffffu, va, off);
                vb += __shfl_xor_sync(0xffffffffu, vb, off);
            }
            if (t == 0) { g_atta[i * 4 + kk] = va; g_attb[i * 4 + kk] = vb; }
        }
    }
}

// ---------------------------------------------------------------------------
// K5: fused (a) t = norm_meta @ f_meta + predictions, (b) full A_meta row
// write (streaming float4 stores; rank-lookup into per-nonzero value list).
// Block per row, 256 threads.
// ---------------------------------------------------------------------------
__global__ void k_post(const float* __restrict__ Wf, const float* __restrict__ bf,
                       float* __restrict__ pred, float* __restrict__ Am) {
    int i = blockIdx.x;
    int t = threadIdx.x;                       // 256 threads
    int lane = t & 31, warp = t >> 5;
    int d4 = t & 3, sub = t >> 2;              // 64 subs
    __shared__ unsigned s_w[WPRP];
    __shared__ int s_cntw[WPRP];
    __shared__ int s_base[WPRP];
    __shared__ int s_list[384];
    __shared__ int s_n;
    __shared__ float s_part[8][16];
    __shared__ float s_t[16];
    __shared__ float s_vals[384];
    __shared__ unsigned s_b0[WPR], s_b1[WPR], s_b2[WPR];

    for (int w = t; w < WPR; w += 256) {
        s_b0[w] = g_bits[0][i * WPRP + w];
        s_b1[w] = g_bits[1][i * WPRP + w];
        s_b2[w] = g_bits[2][i * WPRP + w];
    }

    build_list<256>(g_union + i * WPRP, t, s_w, s_cntw, s_base, s_list, &s_n);
    int E = s_n;

    // ---- (a) union SpMM ----
    float4 acc = gather4<64>((const float4*)g_fs, s_list, E, sub, d4);
    reduce4(acc, lane, warp, d4, s_part);
    __syncthreads();
    if (t < 16) {
        float di = g_dinvu[i];
        float s = 0.f;
        #pragma unroll
        for (int wq = 0; wq < 8; wq++) s += s_part[wq][t];
        s_t[t] = di * (s + g_fs[i * DOUT + t]);
    }
    __syncthreads();
    if (t < NCLS) {
        float p = bf[t];
        #pragma unroll
        for (int o = 0; o < DOUT; o++)
            p = fmaf(s_t[o], Wf[o * NCLS + t], p);
        pred[i * NCLS + t] = p;
    }

    // ---- (b) per-nonzero attention values ----
    float4 A = *(const float4*)&g_atta[i * 4];
    for (int e = t; e < E; e += 256) {
        int j = s_list[e];
        float4 B = *(const float4*)&g_attb[j * 4];
        float s0 = __expf(fmaxf(A.x + B.x, 0.f));
        float s1 = __expf(fmaxf(A.y + B.y, 0.f));
        float s2 = __expf(fmaxf(A.z + B.z, 0.f));
        int w = j >> 5, b = j & 31;
        float num = (((s_b0[w] >> b) & 1u) ? s0 : 0.f) +
                    (((s_b1[w] >> b) & 1u) ? s1 : 0.f) +
                    (((s_b2[w] >> b) & 1u) ? s2 : 0.f);
        s_vals[e] = __fdividef(num, s0 + s1 + s2);
    }
    __syncthreads();

    // ---- (c) full A_meta row write (streaming) ----
    float4* arow = (float4*)(Am + (size_t)i * NN);
    for (int q = t; q < 1250; q += 256) {
        int w = q >> 3;
        unsigned mw = s_w[w];
        unsigned nib = (mw >> ((q & 7) * 4)) & 0xFu;
        float4 o = make_float4(0.f, 0.f, 0.f, 0.f);
        if (nib) {
            int base = s_base[w];
            int bsh = (q & 7) * 4;
            float v[4] = {0.f, 0.f, 0.f, 0.f};
            #pragma unroll
            for (int c = 0; c < 4; c++) {
                if ((nib >> c) & 1u) {
                    int b = bsh + c;
                    int idx = base + __popc(mw & ((1u << b) - 1u));
                    v[c] = s_vals[idx];
                }
            }
            o = make_float4(v[0], v[1], v[2], v[3]);
        }
        __stcs(arow + q, o);
    }
}

// ---------------------------------------------------------------------------
extern "C" void kernel_launch(void* const* d_in, const int* in_sizes, int n_in,
                              void* d_out, int out_size) {
    const float* features = (const float*)d_in[0];
    const float* adj      = (const float*)d_in[1];
    const float* W_gnn    = (const float*)d_in[2];
    const float* b_gnn    = (const float*)d_in[3];
    const float* att_w    = (const float*)d_in[4];
    const float* W_final  = (const float*)d_in[5];
    const float* b_final  = (const float*)d_in[6];

    float* out   = (float*)d_out;
    float* fmeta = out;                                        // [5000,16]
    float* Ameta = out + (size_t)NN * DOUT;                    // [5000,5000]
    float* pred  = out + (size_t)NN * DOUT + (size_t)NN * NN;  // [5000,100]

    k_bits<<<(3 * NN * WPRP + 255) / 256, 256>>>((const float4*)adj);
    k_union<<<(NN * WQ + 255) / 256, 256>>>();
    k_xw<<<(NN + 15) / 16, 192>>>(features, W_gnn);
    k_hatt<<<NN, 384>>>(b_gnn, att_w, fmeta);
    k_post<<<NN, 256>>>(W_final, b_final, pred, Ameta);
}

// round 12
// speedup vs baseline: 1.3323x; 1.3323x over previous
#include <cuda_runtime.h>
#include <math.h>

// ---------------------------------------------------------------------------
// HSGNN forward, GB300.  Sparse-bitmask pipeline, 5 kernels.
// K1: pure coalesced adj stream -> nibble bytes (no barriers/atomics/shuffles).
// K2: pack nibbles -> mask words + union + degrees.
// ---------------------------------------------------------------------------

#define NN 5000
#define WPR 157      // ceil(5000/32) words per bitmask row
#define WPRP 160     // padded words per row
#define DOUT 16
#define NCLS 100
#define NIBR 1256    // padded nibble-bytes per row (1250 + 6 pad, 8-aligned)
#define NF4 18750000 // 3*NN*1250 float4s in adj

__device__ unsigned char g_nib[3 * NN * NIBR + 16];  // nibble byte per float4
__device__ unsigned g_bits[3][NN * WPRP];   // per-meta-path adjacency bitmasks
__device__ unsigned g_union[NN * WPRP];     // union pattern
__device__ float    g_dinv[3][NN];          // D^{-1/2} per meta-path
__device__ float    g_dinvu[NN];            // D^{-1/2} for union pattern
__device__ float    g_XWs[3][NN * DOUT];    // dinv[k][i] * (features @ W_gnn[k])[i]
__device__ float    g_fs[NN * DOUT];        // dinvu[i] * f_meta[i]
__device__ float    g_atta[NN * 4];         // a[i,k] (padded stride 4)
__device__ float    g_attb[NN * 4];         // b[j,k]

// ---------------------------------------------------------------------------
// K1: memcpy-shaped scan.  Thread handles 4 block-strided float4s: coalesced
// LDG.128 stream + 1-byte nibble store each.  Also zeroes the 6 pad bytes/row.
// ---------------------------------------------------------------------------
__global__ void k_bits(const float4* __restrict__ adj4) {
    int flat = blockIdx.x * 256 + threadIdx.x;
    if (flat < 3 * NN * 6) {                 // zero row pad bytes
        int r = flat / 6, p = flat - r * 6;
        g_nib[r * NIBR + 1250 + p] = 0;
    }
    int base = blockIdx.x * 1024 + threadIdx.x;
    #pragma unroll
    for (int q = 0; q < 4; q++) {
        int x = base + q * 256;
        if (x < NF4) {
            float4 v = __ldcs(adj4 + x);
            unsigned nb = (v.x != 0.f ? 1u : 0u) | (v.y != 0.f ? 2u : 0u) |
                          (v.z != 0.f ? 4u : 0u) | (v.w != 0.f ? 8u : 0u);
            int r = x / 1250;                // r = k*NN + i
            int c = x - r * 1250;
            g_nib[r * NIBR + c] = (unsigned char)nb;
        }
    }
}

// ---------------------------------------------------------------------------
// K2: block per row i (160 threads).  t<157: pack 8 nibble-bytes -> word for
// each k, OR -> union, write all 4 arrays; smem popc reduction -> dinv.
// ---------------------------------------------------------------------------
__global__ void k_union() {
    int i = blockIdx.x;
    int t = threadIdx.x;                     // 160 threads
    __shared__ int s_cnt[4];
    if (t < 4) s_cnt[t] = 0;
    __syncthreads();
    if (t < WPR) {
        unsigned b[3];
        #pragma unroll
        for (int k = 0; k < 3; k++) {
            const uint2* p = (const uint2*)&g_nib[((size_t)k * NN + i) * NIBR];
            uint2 xy = p[t];
            unsigned x = xy.x, y = xy.y;
            x = (x | (x >> 4)) & 0x00FF00FFu;
            x = (x | (x >> 8)) & 0x0000FFFFu;
            y = (y | (y >> 4)) & 0x00FF00FFu;
            y = (y | (y >> 8)) & 0x0000FFFFu;
            b[k] = x | (y << 16);
        }
        unsigned u = b[0] | b[1] | b[2];
        g_bits[0][i * WPRP + t] = b[0];
        g_bits[1][i * WPRP + t] = b[1];
        g_bits[2][i * WPRP + t] = b[2];
        g_union[i * WPRP + t] = u;
        if (b[0]) atomicAdd(&s_cnt[0], __popc(b[0]));
        if (b[1]) atomicAdd(&s_cnt[1], __popc(b[1]));
        if (b[2]) atomicAdd(&s_cnt[2], __popc(b[2]));
        if (u)    atomicAdd(&s_cnt[3], __popc(u));
    } else {
        g_bits[0][i * WPRP + t] = 0;
        g_bits[1][i * WPRP + t] = 0;
        g_bits[2][i * WPRP + t] = 0;
        g_union[i * WPRP + t] = 0;
    }
    __syncthreads();
    if (t < 3) g_dinv[t][i] = rsqrtf((float)(s_cnt[t] + 1));
    if (t == 3) g_dinvu[i] = rsqrtf((float)(s_cnt[3] + 1));
}

// ---------------------------------------------------------------------------
// K3: XWs[k][i] = dinv[k][i] * (features[i] @ W_gnn[k]).  Register tile:
// 4 rows/thread share each W load; features staged in smem.
// ---------------------------------------------------------------------------
__global__ void k_xw(const float* __restrict__ feat, const float* __restrict__ W) {
    __shared__ float sf[16 * 512];             // 32 KB
    int i0 = blockIdx.x * 16;
    for (int x = threadIdx.x; x < 16 * 128; x += 192) {
        int r = x >> 7, c = x & 127;
        int gi = i0 + r;
        float4 v = make_float4(0.f, 0.f, 0.f, 0.f);
        if (gi < NN) v = ((const float4*)feat)[(size_t)gi * 128 + c];
        ((float4*)sf)[x] = v;
    }
    __syncthreads();

    int t = threadIdx.x;
    int o = t & 15;
    int k = (t >> 4) % 3;
    int rq = t / 48;                           // 0..3
    const float* wp = W + k * (512 * 16) + o;
    const float* f0 = sf + (rq * 4 + 0) * 512;
    const float* f1 = f0 + 512;
    const float* f2 = f1 + 512;
    const float* f3 = f2 + 512;
    float a0 = 0.f, a1 = 0.f, a2 = 0.f, a3 = 0.f;
    #pragma unroll 4
    for (int d = 0; d < 512; d += 4) {
        float w0 = wp[(d + 0) * 16];
        float w1 = wp[(d + 1) * 16];
        float w2 = wp[(d + 2) * 16];
        float w3 = wp[(d + 3) * 16];
        float4 x0 = *(const float4*)(f0 + d);
        float4 x1 = *(const float4*)(f1 + d);
        float4 x2 = *(const float4*)(f2 + d);
        float4 x3 = *(const float4*)(f3 + d);
        a0 = fmaf(x0.x, w0, fmaf(x0.y, w1, fmaf(x0.z, w2, fmaf(x0.w, w3, a0))));
        a1 = fmaf(x1.x, w0, fmaf(x1.y, w1, fmaf(x1.z, w2, fmaf(x1.w, w3, a1))));
        a2 = fmaf(x2.x, w0, fmaf(x2.y, w1, fmaf(x2.z, w2, fmaf(x2.w, w3, a2))));
        a3 = fmaf(x3.x, w0, fmaf(x3.y, w1, fmaf(x3.z, w2, fmaf(x3.w, w3, a3))));
    }
    int gi = i0 + rq * 4;
    if (gi + 0 < NN) g_XWs[k][(gi + 0) * DOUT + o] = a0 * g_dinv[k][gi + 0];
    if (gi + 1 < NN) g_XWs[k][(gi + 1) * DOUT + o] = a1 * g_dinv[k][gi + 1];
    if (gi + 2 < NN) g_XWs[k][(gi + 2) * DOUT + o] = a2 * g_dinv[k][gi + 2];
    if (gi + 3 < NN) g_XWs[k][(gi + 3) * DOUT + o] = a3 * g_dinv[k][gi + 3];
}

// ---------------------------------------------------------------------------
// Deterministic nonzero-list build within an NT-thread group.
// ---------------------------------------------------------------------------
template <int NT>
__device__ __forceinline__ void build_list(const unsigned* __restrict__ src, int lt,
                                           unsigned* s_w, int* s_cntw, int* s_base,
                                           int* s_list, int* s_n) {
    for (int w = lt; w < WPRP; w += NT) {
        unsigned m = (w < WPR) ? src[w] : 0u;
        s_w[w] = m;
        s_cntw[w] = __popc(m);
    }
    __syncthreads();
    if (lt < 32) {
        int run = 0;
        #pragma unroll
        for (int g = 0; g < 5; g++) {
            int w = g * 32 + lt;
            int c = s_cntw[w];
            int x = c;
            #pragma unroll
            for (int off = 1; off < 32; off <<= 1) {
                int y = __shfl_up_sync(0xffffffffu, x, off);
                if (lt >= off) x += y;
            }
            s_base[w] = run + x - c;
            run += __shfl_sync(0xffffffffu, x, 31);
        }
        if (lt == 0) *s_n = run;
    }
    __syncthreads();
    for (int w = lt; w < WPR; w += NT) {
        unsigned m = s_w[w];
        int base = s_base[w];
        int jb = w * 32;
        while (m) {
            int b = __ffs(m) - 1; m &= m - 1;
            s_list[base++] = jb + b;
        }
    }
    __syncthreads();
}

// float4 gather-accumulate over list, SUBS parallel streams, 2-deep pipeline.
template <int SUBS>
__device__ __forceinline__ float4 gather4(const float4* __restrict__ X4,
                                          const int* __restrict__ list,
                                          int E, int sub, int d4) {
    float4 a0 = make_float4(0.f, 0.f, 0.f, 0.f);
    float4 a1 = make_float4(0.f, 0.f, 0.f, 0.f);
    int e = sub;
    for (; e + SUBS < E; e += 2 * SUBS) {
        int j0 = list[e], j1 = list[e + SUBS];
        float4 v0 = X4[j0 * 4 + d4];
        float4 v1 = X4[j1 * 4 + d4];
        a0.x += v0.x; a0.y += v0.y; a0.z += v0.z; a0.w += v0.w;
        a1.x += v1.x; a1.y += v1.y; a1.z += v1.z; a1.w += v1.w;
    }
    if (e < E) {
        float4 v = X4[list[e] * 4 + d4];
        a0.x += v.x; a0.y += v.y; a0.z += v.z; a0.w += v.w;
    }
    a0.x += a1.x; a0.y += a1.y; a0.z += a1.z; a0.w += a1.w;
    return a0;
}

// Reduce within warp (8 subs x float4) -> s_part[warp][16].
__device__ __forceinline__ void reduce4(float4 acc, int lane, int warp, int d4,
                                        float (*s_part)[16]) {
    #pragma unroll
    for (int off = 4; off < 32; off <<= 1) {
        acc.x += __shfl_xor_sync(0xffffffffu, acc.x, off);
        acc.y += __shfl_xor_sync(0xffffffffu, acc.y, off);
        acc.z += __shfl_xor_sync(0xffffffffu, acc.z, off);
        acc.w += __shfl_xor_sync(0xffffffffu, acc.w, off);
    }
    if (lane < 4) {
        s_part[warp][d4 * 4 + 0] = acc.x;
        s_part[warp][d4 * 4 + 1] = acc.y;
        s_part[warp][d4 * 4 + 2] = acc.z;
        s_part[warp][d4 * 4 + 3] = acc.w;
    }
}

// ---------------------------------------------------------------------------
// K4: 3 meta-path GCN convs (warpgroup per k) + max -> f_meta, scaled f_s,
// attention projections. Block per row, 384 threads.
// ---------------------------------------------------------------------------
__global__ void k_hatt(const float* __restrict__ bgnn, const float* __restrict__ attw,
                       float* __restrict__ fmeta) {
    int i = blockIdx.x;
    int t = threadIdx.x;
    int k = t >> 7;               // warpgroup = meta-path
    int lt = t & 127;
    int lane = lt & 31, warp = lt >> 5;
    int d4 = lt & 3, sub = lt >> 2;

    __shared__ unsigned s_w[3][WPRP];
    __shared__ int s_cntw[3][WPRP];
    __shared__ int s_base[3][WPRP];
    __shared__ int s_list[3][320];
    __shared__ int s_n[3];
    __shared__ float s_part[3][4][16];
    __shared__ float s_h[3][16];

    build_list<128>(&g_bits[k][i * WPRP], lt, s_w[k], s_cntw[k], s_base[k],
                    s_list[k], &s_n[k]);

    float4 acc = gather4<32>((const float4*)g_XWs[k], s_list[k], s_n[k], sub, d4);
    reduce4(acc, lane, warp, d4, s_part[k]);
    __syncthreads();

    if (lt < 16) {
        const float* Xs = g_XWs[k];
        float s = s_part[k][0][lt] + s_part[k][1][lt] +
                  s_part[k][2][lt] + s_part[k][3][lt];
        float di = g_dinv[k][i];
        s_h[k][lt] = fmaf(di, s + Xs[i * DOUT + lt], bgnn[k * 16 + lt]);
    }
    __syncthreads();

    if (t < 32) {
        float best = 0.f;
        if (t < 16) {
            best = fmaxf(s_h[0][t], fmaxf(s_h[1][t], s_h[2][t]));
            fmeta[i * DOUT + t] = best;
            g_fs[i * DOUT + t] = g_dinvu[i] * best;
        }
        #pragma unroll
        for (int kk = 0; kk < 3; kk++) {
            float va = (t < 16) ? best * attw[kk * 32 + t] : 0.f;
            float vb = (t < 16) ? best * attw[kk * 32 + 16 + t] : 0.f;
            #pragma unroll
            for (int off = 8; off >= 1; off >>= 1) {
                va += __shfl_xor_sync(0xffffffffu, va, off);
                vb += __shfl_xor_sync(0xffffffffu, vb, off);
            }
            if (t == 0) { g_atta[i * 4 + kk] = va; g_attb[i * 4 + kk] = vb; }
        }
    }
}

// ---------------------------------------------------------------------------
// K5: fused (a) t = norm_meta @ f_meta + predictions, (b) full A_meta row
// write (streaming float4 stores; rank-lookup into per-nonzero value list).
// Block per row, 256 threads.
// ---------------------------------------------------------------------------
__global__ void k_post(const float* __restrict__ Wf, const float* __restrict__ bf,
                       float* __restrict__ pred, float* __restrict__ Am) {
    int i = blockIdx.x;
    int t = threadIdx.x;                       // 256 threads
    int lane = t & 31, warp = t >> 5;
    int d4 = t & 3, sub = t >> 2;              // 64 subs
    __shared__ unsigned s_w[WPRP];
    __shared__ int s_cntw[WPRP];
    __shared__ int s_base[WPRP];
    __shared__ int s_list[384];
    __shared__ int s_n;
    __shared__ float s_part[8][16];
    __shared__ float s_t[16];
    __shared__ float s_vals[384];
    __shared__ unsigned s_b0[WPR], s_b1[WPR], s_b2[WPR];

    for (int w = t; w < WPR; w += 256) {
        s_b0[w] = g_bits[0][i * WPRP + w];
        s_b1[w] = g_bits[1][i * WPRP + w];
        s_b2[w] = g_bits[2][i * WPRP + w];
    }

    build_list<256>(g_union + i * WPRP, t, s_w, s_cntw, s_base, s_list, &s_n);
    int E = s_n;

    // ---- (a) union SpMM ----
    float4 acc = gather4<64>((const float4*)g_fs, s_list, E, sub, d4);
    reduce4(acc, lane, warp, d4, s_part);
    __syncthreads();
    if (t < 16) {
        float di = g_dinvu[i];
        float s = 0.f;
        #pragma unroll
        for (int wq = 0; wq < 8; wq++) s += s_part[wq][t];
        s_t[t] = di * (s + g_fs[i * DOUT + t]);
    }
    __syncthreads();
    if (t < NCLS) {
        float p = bf[t];
        #pragma unroll
        for (int o = 0; o < DOUT; o++)
            p = fmaf(s_t[o], Wf[o * NCLS + t], p);
        pred[i * NCLS + t] = p;
    }

    // ---- (b) per-nonzero attention values ----
    float4 A = *(const float4*)&g_atta[i * 4];
    for (int e = t; e < E; e += 256) {
        int j = s_list[e];
        float4 B = *(const float4*)&g_attb[j * 4];
        float s0 = __expf(fmaxf(A.x + B.x, 0.f));
        float s1 = __expf(fmaxf(A.y + B.y, 0.f));
        float s2 = __expf(fmaxf(A.z + B.z, 0.f));
        int w = j >> 5, b = j & 31;
        float num = (((s_b0[w] >> b) & 1u) ? s0 : 0.f) +
                    (((s_b1[w] >> b) & 1u) ? s1 : 0.f) +
                    (((s_b2[w] >> b) & 1u) ? s2 : 0.f);
        s_vals[e] = __fdividef(num, s0 + s1 + s2);
    }
    __syncthreads();

    // ---- (c) full A_meta row write (streaming) ----
    float4* arow = (float4*)(Am + (size_t)i * NN);
    for (int q = t; q < 1250; q += 256) {
        int w = q >> 3;
        unsigned mw = s_w[w];
        unsigned nib = (mw >> ((q & 7) * 4)) & 0xFu;
        float4 o = make_float4(0.f, 0.f, 0.f, 0.f);
        if (nib) {
            int base = s_base[w];
            int bsh = (q & 7) * 4;
            float v[4] = {0.f, 0.f, 0.f, 0.f};
            #pragma unroll
            for (int c = 0; c < 4; c++) {
                if ((nib >> c) & 1u) {
                    int b = bsh + c;
                    int idx = base + __popc(mw & ((1u << b) - 1u));
                    v[c] = s_vals[idx];
                }
            }
            o = make_float4(v[0], v[1], v[2], v[3]);
        }
        __stcs(arow + q, o);
    }
}

// ---------------------------------------------------------------------------
extern "C" void kernel_launch(void* const* d_in, const int* in_sizes, int n_in,
                              void* d_out, int out_size) {
    const float* features = (const float*)d_in[0];
    const float* adj      = (const float*)d_in[1];
    const float* W_gnn    = (const float*)d_in[2];
    const float* b_gnn    = (const float*)d_in[3];
    const float* att_w    = (const float*)d_in[4];
    const float* W_final  = (const float*)d_in[5];
    const float* b_final  = (const float*)d_in[6];

    float* out   = (float*)d_out;
    float* fmeta = out;                                        // [5000,16]
    float* Ameta = out + (size_t)NN * DOUT;                    // [5000,5000]
    float* pred  = out + (size_t)NN * DOUT + (size_t)NN * NN;  // [5000,100]

    k_bits<<<(NF4 + 1023) / 1024, 256>>>((const float4*)adj);
    k_union<<<NN, 160>>>();
    k_xw<<<(NN + 15) / 16, 192>>>(features, W_gnn);
    k_hatt<<<NN, 384>>>(b_gnn, att_w, fmeta);
    k_post<<<NN, 256>>>(W_final, b_final, pred, Ameta);
}

// round 13
// speedup vs baseline: 1.4360x; 1.0779x over previous
#include <cuda_runtime.h>
#include <math.h>

// ---------------------------------------------------------------------------
// HSGNN forward, GB300.  Sparse-bitmask pipeline, 3 kernels.
// K1: R8 fused prep (best measured pass-1: 78 us).
// K2/K3: parallel multi-warp list-build scan (was 5 sequential warp scans).
// ---------------------------------------------------------------------------

#define NN 5000
#define WPR 157      // ceil(5000/32) words per bitmask row
#define WPRP 160     // padded words per row (= 5 chunks of 32)
#define DOUT 16
#define NCLS 100

__device__ unsigned g_bits[3][NN * WPRP];   // per-meta-path adjacency bitmasks
__device__ unsigned g_union[NN * WPRP];     // union pattern
__device__ float    g_dinv[3][NN];          // D^{-1/2} per meta-path
__device__ float    g_dinvu[NN];            // D^{-1/2} for union pattern
__device__ float    g_XWs[3][NN * DOUT];    // dinv[k][i] * (features @ W_gnn[k])[i]
__device__ float    g_fs[NN * DOUT];        // dinvu[i] * f_meta[i]
__device__ float    g_atta[NN * 4];         // a[i,k] (padded stride 4)
__device__ float    g_attb[NN * 4];         // b[j,k]

// ---------------------------------------------------------------------------
// K1: per row i — 3 sequential 5-deep load batches; nibble -> shuffle-OR ->
// one STS per word; XW fused after.  256 threads (R8 structure, 78 us).
// ---------------------------------------------------------------------------
__global__ void k_prep(const float* __restrict__ adj, const float* __restrict__ feat,
                       const float* __restrict__ W) {
    int i = blockIdx.x;
    int t = threadIdx.x;                       // 256 threads
    __shared__ float s_f[512];
    __shared__ unsigned s_b[3][WPRP + 3];
    __shared__ int s_cnt[4];
    __shared__ float s_xw[48][4];
    __shared__ float s_dinv[3];

    if (t < 4) s_cnt[t] = 0;
    if (t < 128) ((float4*)s_f)[t] = ((const float4*)(feat + (size_t)i * 512))[t];

    int bsh = (t & 7) * 4;                     // nibble position within word

    #pragma unroll
    for (int k = 0; k < 3; k++) {
        const float4* rp = (const float4*)(adj + ((size_t)k * NN + i) * NN);
        float4 v[5];
        #pragma unroll
        for (int u = 0; u < 5; u++) {
            int q = t + 256 * u;
            if (q < 1250) v[u] = __ldcs(rp + q);
            else          v[u] = make_float4(0.f, 0.f, 0.f, 0.f);
        }
        #pragma unroll
        for (int u = 0; u < 5; u++) {
            int q = t + 256 * u;
            unsigned nb = (v[u].x != 0.f ? 1u : 0u) | (v[u].y != 0.f ? 2u : 0u) |
                          (v[u].z != 0.f ? 4u : 0u) | (v[u].w != 0.f ? 8u : 0u);
            unsigned x = nb << bsh;
            x |= __shfl_xor_sync(0xffffffffu, x, 1);
            x |= __shfl_xor_sync(0xffffffffu, x, 2);
            x |= __shfl_xor_sync(0xffffffffu, x, 4);
            if ((t & 7) == 0) s_b[k][q >> 3] = x;
        }
    }
    __syncthreads();

    // XW partials: 192 threads = (part:4) x (k:3) x (o:16), 128 dims each
    if (t < 192) {
        int o = t & 15, k = (t >> 4) % 3, part = t / 48;
        const float* wp = W + k * (512 * 16) + o;
        const float* fp = s_f + part * 128;
        float a = 0.f;
        #pragma unroll 8
        for (int d = 0; d < 128; d++)
            a = fmaf(fp[d], wp[(part * 128 + d) * 16], a);
        s_xw[k * 16 + o][part] = a;
    }
    if (t < WPR) {
        unsigned b0 = s_b[0][t], b1 = s_b[1][t], b2 = s_b[2][t];
        unsigned u = b0 | b1 | b2;
        g_bits[0][i * WPRP + t] = b0;
        g_bits[1][i * WPRP + t] = b1;
        g_bits[2][i * WPRP + t] = b2;
        g_union[i * WPRP + t] = u;
        if (b0) atomicAdd(&s_cnt[0], __popc(b0));
        if (b1) atomicAdd(&s_cnt[1], __popc(b1));
        if (b2) atomicAdd(&s_cnt[2], __popc(b2));
        if (u)  atomicAdd(&s_cnt[3], __popc(u));
    }
    __syncthreads();
    if (t < 3) {
        float dv = rsqrtf((float)(s_cnt[t] + 1));
        s_dinv[t] = dv;
        g_dinv[t][i] = dv;
    }
    if (t == 3) g_dinvu[i] = rsqrtf((float)(s_cnt[3] + 1));
    __syncthreads();
    if (t < 48) {
        int k = t >> 4, o = t & 15;
        float s = s_xw[t][0] + s_xw[t][1] + s_xw[t][2] + s_xw[t][3];
        g_XWs[k][i * DOUT + o] = s * s_dinv[k];
    }
}

// ---------------------------------------------------------------------------
// Parallel list build: 5 word-chunks scanned on NT/32 warps concurrently,
// 5-element level-2 scan, then offset emit.  s_csum[8] scratch.
// ---------------------------------------------------------------------------
template <int NT>
__device__ __forceinline__ void build_list2(const unsigned* __restrict__ src, int lt,
                                            unsigned* s_w, int* s_base, int* s_csum,
                                            int* s_list, int* s_n) {
    for (int w = lt; w < WPRP; w += NT) {
        unsigned m = (w < WPR) ? src[w] : 0u;
        s_w[w] = m;
    }
    __syncthreads();
    int warp = lt >> 5, lane = lt & 31;
    const int NW = NT / 32;
    for (int ch = warp; ch < 5; ch += NW) {
        int w = ch * 32 + lane;
        int c = __popc(s_w[w]);
        int x = c;
        #pragma unroll
        for (int off = 1; off < 32; off <<= 1) {
            int y = __shfl_up_sync(0xffffffffu, x, off);
            if (lane >= off) x += y;
        }
        s_base[w] = x - c;
        if (lane == 31) s_csum[ch] = x;
    }
    __syncthreads();
    if (lt < 32) {
        int v = (lane < 5) ? s_csum[lane] : 0;
        int x = v;
        #pragma unroll
        for (int off = 1; off < 8; off <<= 1) {
            int y = __shfl_up_sync(0xffffffffu, x, off);
            if (lane >= off) x += y;
        }
        if (lane < 5) s_csum[lane] = x - v;       // exclusive chunk offsets
        if (lane == 4) *s_n = x;                  // total
    }
    __syncthreads();
    for (int w = lt; w < WPR; w += NT) {
        unsigned m = s_w[w];
        int base = s_base[w] + s_csum[w >> 5];
        int jb = w * 32;
        while (m) {
            int b = __ffs(m) - 1; m &= m - 1;
            s_list[base++] = jb + b;
        }
    }
    __syncthreads();
}

// float4 gather-accumulate over list, SUBS parallel streams, 2-deep pipeline.
template <int SUBS>
__device__ __forceinline__ float4 gather4(const float4* __restrict__ X4,
                                          const int* __restrict__ list,
                                          int E, int sub, int d4) {
    float4 a0 = make_float4(0.f, 0.f, 0.f, 0.f);
    float4 a1 = make_float4(0.f, 0.f, 0.f, 0.f);
    int e = sub;
    for (; e + SUBS < E; e += 2 * SUBS) {
        int j0 = list[e], j1 = list[e + SUBS];
        float4 v0 = X4[j0 * 4 + d4];
        float4 v1 = X4[j1 * 4 + d4];
        a0.x += v0.x; a0.y += v0.y; a0.z += v0.z; a0.w += v0.w;
        a1.x += v1.x; a1.y += v1.y; a1.z += v1.z; a1.w += v1.w;
    }
    if (e < E) {
        float4 v = X4[list[e] * 4 + d4];
        a0.x += v.x; a0.y += v.y; a0.z += v.z; a0.w += v.w;
    }
    a0.x += a1.x; a0.y += a1.y; a0.z += a1.z; a0.w += a1.w;
    return a0;
}

// Reduce within warp (8 subs x float4) -> s_part[warp][16].
__device__ __forceinline__ void reduce4(float4 acc, int lane, int warp, int d4,
                                        float (*s_part)[16]) {
    #pragma unroll
    for (int off = 4; off < 32; off <<= 1) {
        acc.x += __shfl_xor_sync(0xffffffffu, acc.x, off);
        acc.y += __shfl_xor_sync(0xffffffffu, acc.y, off);
        acc.z += __shfl_xor_sync(0xffffffffu, acc.z, off);
        acc.w += __shfl_xor_sync(0xffffffffu, acc.w, off);
    }
    if (lane < 4) {
        s_part[warp][d4 * 4 + 0] = acc.x;
        s_part[warp][d4 * 4 + 1] = acc.y;
        s_part[warp][d4 * 4 + 2] = acc.z;
        s_part[warp][d4 * 4 + 3] = acc.w;
    }
}

// ---------------------------------------------------------------------------
// K2: 3 meta-path GCN convs (warpgroup per k) + max -> f_meta, scaled f_s,
// attention projections (one warp per k). Block per row, 384 threads.
// ---------------------------------------------------------------------------
__global__ void k_hatt(const float* __restrict__ bgnn, const float* __restrict__ attw,
                       float* __restrict__ fmeta) {
    int i = blockIdx.x;
    int t = threadIdx.x;
    int k = t >> 7;               // warpgroup = meta-path
    int lt = t & 127;
    int lane = lt & 31, warp = lt >> 5;
    int d4 = lt & 3, sub = lt >> 2;

    __shared__ unsigned s_w[3][WPRP];
    __shared__ int s_base[3][WPRP];
    __shared__ int s_csum[3][8];
    __shared__ int s_list[3][320];
    __shared__ int s_n[3];
    __shared__ float s_part[3][4][16];
    __shared__ float s_h[3][16];
    __shared__ float s_best[16];

    build_list2<128>(&g_bits[k][i * WPRP], lt, s_w[k], s_base[k], s_csum[k],
                     s_list[k], &s_n[k]);

    float4 acc = gather4<32>((const float4*)g_XWs[k], s_list[k], s_n[k], sub, d4);
    reduce4(acc, lane, warp, d4, s_part[k]);
    __syncthreads();

    if (lt < 16) {
        const float* Xs = g_XWs[k];
        float s = s_part[k][0][lt] + s_part[k][1][lt] +
                  s_part[k][2][lt] + s_part[k][3][lt];
        float di = g_dinv[k][i];
        s_h[k][lt] = fmaf(di, s + Xs[i * DOUT + lt], bgnn[k * 16 + lt]);
    }
    __syncthreads();

    if (t < 16) {
        float best = fmaxf(s_h[0][t], fmaxf(s_h[1][t], s_h[2][t]));
        s_best[t] = best;
        fmeta[i * DOUT + t] = best;
        g_fs[i * DOUT + t] = g_dinvu[i] * best;
    }
    __syncthreads();

    // attention projections: warp kk handles meta-path kk (3 warps parallel)
    if (t < 96) {
        int kk = t >> 5;
        int l = t & 31;
        float best = (l < 16) ? s_best[l] : 0.f;
        float va = (l < 16) ? best * attw[kk * 32 + l] : 0.f;
        float vb = (l < 16) ? best * attw[kk * 32 + 16 + l] : 0.f;
        #pragma unroll
        for (int off = 8; off >= 1; off >>= 1) {
            va += __shfl_xor_sync(0xffffffffu, va, off);
            vb += __shfl_xor_sync(0xffffffffu, vb, off);
        }
        if (l == 0) { g_atta[i * 4 + kk] = va; g_attb[i * 4 + kk] = vb; }
    }
}

// ---------------------------------------------------------------------------
// K3: fused (a) t = norm_meta @ f_meta + predictions, (b) full A_meta row
// write.  Block per row, 256 threads (8 warps -> fully parallel scan).
// ---------------------------------------------------------------------------
__global__ void k_post(const float* __restrict__ Wf, const float* __restrict__ bf,
                       float* __restrict__ pred, float* __restrict__ Am) {
    int i = blockIdx.x;
    int t = threadIdx.x;                       // 256 threads
    int lane = t & 31, warp = t >> 5;
    int d4 = t & 3, sub = t >> 2;              // 64 subs
    __shared__ unsigned s_w[WPRP];
    __shared__ int s_base[WPRP];
    __shared__ int s_csum[8];
    __shared__ int s_list[384];
    __shared__ int s_n;
    __shared__ float s_part[8][16];
    __shared__ float s_t[16];
    __shared__ float s_vals[384];
    __shared__ unsigned s_b0[WPR], s_b1[WPR], s_b2[WPR];

    for (int w = t; w < WPR; w += 256) {
        s_b0[w] = g_bits[0][i * WPRP + w];
        s_b1[w] = g_bits[1][i * WPRP + w];
        s_b2[w] = g_bits[2][i * WPRP + w];
    }

    build_list2<256>(g_union + i * WPRP, t, s_w, s_base, s_csum, s_list, &s_n);
    int E = s_n;

    // ---- (a) union SpMM ----
    float4 acc = gather4<64>((const float4*)g_fs, s_list, E, sub, d4);
    reduce4(acc, lane, warp, d4, s_part);
    __syncthreads();
    if (t < 16) {
        float di = g_dinvu[i];
        float s = 0.f;
        #pragma unroll
        for (int wq = 0; wq < 8; wq++) s += s_part[wq][t];
        s_t[t] = di * (s + g_fs[i * DOUT + t]);
    }
    __syncthreads();
    if (t < NCLS) {
        float p = bf[t];
        #pragma unroll
        for (int o = 0; o < DOUT; o++)
            p = fmaf(s_t[o], Wf[o * NCLS + t], p);
        pred[i * NCLS + t] = p;
    }

    // ---- (b) per-nonzero attention values ----
    float4 A = *(const float4*)&g_atta[i * 4];
    for (int e = t; e < E; e += 256) {
        int j = s_list[e];
        float4 B = *(const float4*)&g_attb[j * 4];
        float s0 = __expf(fmaxf(A.x + B.x, 0.f));
        float s1 = __expf(fmaxf(A.y + B.y, 0.f));
        float s2 = __expf(fmaxf(A.z + B.z, 0.f));
        int w = j >> 5, b = j & 31;
        float num = (((s_b0[w] >> b) & 1u) ? s0 : 0.f) +
                    (((s_b1[w] >> b) & 1u) ? s1 : 0.f) +
                    (((s_b2[w] >> b) & 1u) ? s2 : 0.f);
        s_vals[e] = __fdividef(num, s0 + s1 + s2);
    }
    __syncthreads();

    // ---- (c) full A_meta row write (streaming) ----
    float4* arow = (float4*)(Am + (size_t)i * NN);
    for (int q = t; q < 1250; q += 256) {
        int w = q >> 3;
        unsigned mw = s_w[w];
        unsigned nib = (mw >> ((q & 7) * 4)) & 0xFu;
        float4 o = make_float4(0.f, 0.f, 0.f, 0.f);
        if (nib) {
            int base = s_base[w] + s_csum[w >> 5];
            int bsh = (q & 7) * 4;
            float v[4] = {0.f, 0.f, 0.f, 0.f};
            #pragma unroll
            for (int c = 0; c < 4; c++) {
                if ((nib >> c) & 1u) {
                    int b = bsh + c;
                    int idx = base + __popc(mw & ((1u << b) - 1u));
                    v[c] = s_vals[idx];
                }
            }
            o = make_float4(v[0], v[1], v[2], v[3]);
        }
        __stcs(arow + q, o);
    }
}

// ---------------------------------------------------------------------------
extern "C" void kernel_launch(void* const* d_in, const int* in_sizes, int n_in,
                              void* d_out, int out_size) {
    const float* features = (const float*)d_in[0];
    const float* adj      = (const float*)d_in[1];
    const float* W_gnn    = (const float*)d_in[2];
    const float* b_gnn    = (const float*)d_in[3];
    const float* att_w    = (const float*)d_in[4];
    const float* W_final  = (const float*)d_in[5];
    const float* b_final  = (const float*)d_in[6];

    float* out   = (float*)d_out;
    float* fmeta = out;                                        // [5000,16]
    float* Ameta = out + (size_t)NN * DOUT;                    // [5000,5000]
    float* pred  = out + (size_t)NN * DOUT + (size_t)NN * NN;  // [5000,100]

    k_prep<<<NN, 256>>>(adj, features, W_gnn);
    k_hatt<<<NN, 384>>>(b_gnn, att_w, fmeta);
    k_post<<<NN, 256>>>(W_final, b_final, pred, Ameta);
}